// round 11
// baseline (speedup 1.0000x reference)
#include <cuda_runtime.h>
#include <cuda_fp16.h>
#include <cstdint>

#define K_DIM 4096
#define M_DIM 8192
#define N_DIM 4096

// GEMM tiling: BM=128, BN=256, BK=64 halfs (128B rows), 512 threads (4x4 warps)
#define BM 128
#define BN 256
#define KIT 64                     // K / 64
#define A_TILE 16384               // 128 rows x 128B
#define B_TILE 32768               // 256 rows x 128B
#define STAGE_BYTES (A_TILE + B_TILE)
#define NSTG 4
#define OFF_TAB (NSTG * STAGE_BYTES)
#define SMEM_TOTAL (OFF_TAB + 256 * 8)

// ---------------- scratch (allocation-free) ----------------
__device__ __align__(16) __half g_Wh[(size_t)N_DIM * K_DIM];  // 32MB [N][K]
__device__ __align__(16) __half g_Xh[(size_t)M_DIM * K_DIM];  // 64MB [M][K], holds (Xq - zp)
__device__ float g_wscale[N_DIM];
__device__ float g_ascale[M_DIM];

// ---------------- PTX helpers (base-target safe) ----------------
__device__ __forceinline__ uint32_t smem_u32(const void* p) {
    uint32_t a;
    asm("{ .reg .u64 t; cvta.to.shared.u64 t, %1; cvt.u32.u64 %0, t; }" : "=r"(a) : "l"(p));
    return a;
}
__device__ __forceinline__ void cp_async16(uint32_t dst, const void* src) {
    asm volatile("cp.async.cg.shared.global [%0], [%1], 16;" :: "r"(dst), "l"(src));
}
#define CP_COMMIT() asm volatile("cp.async.commit_group;" ::: "memory")
#define CP_WAIT2()  asm volatile("cp.async.wait_group 2;" ::: "memory")

__device__ __forceinline__ void ldsm_x4(uint32_t addr, uint32_t& r0, uint32_t& r1,
                                        uint32_t& r2, uint32_t& r3) {
    asm volatile("ldmatrix.sync.aligned.m8n8.x4.shared.b16 {%0,%1,%2,%3}, [%4];"
                 : "=r"(r0), "=r"(r1), "=r"(r2), "=r"(r3) : "r"(addr));
}
__device__ __forceinline__ void mma_f16(float* c, const uint32_t* a, uint32_t b0, uint32_t b1) {
    asm volatile("mma.sync.aligned.m16n8k16.row.col.f32.f16.f16.f32 "
                 "{%0,%1,%2,%3}, {%4,%5,%6,%7}, {%8,%9}, {%0,%1,%2,%3};"
                 : "+f"(c[0]), "+f"(c[1]), "+f"(c[2]), "+f"(c[3])
                 : "r"(a[0]), "r"(a[1]), "r"(a[2]), "r"(a[3]), "r"(b0), "r"(b1));
}

// ---------------- fused quantization ----------------
// blocks [0, N) -> weight rows; blocks [N, N+M) -> activation tokens.
// Weight: symmetric int8 (absmax/127) stored as fp16 integers + scale.
// Activation: asymmetric uint8; stores (Xq - zp) as fp16 -> no zp term in GEMM.
__global__ __launch_bounds__(256) void quant_kernel(const float* __restrict__ W,
                                                    const float* __restrict__ X) {
    const int b = blockIdx.x;
    const int t = threadIdx.x, wid = t >> 5, lid = t & 31;
    __shared__ float smn[8], smx[8];

    if (b < N_DIM) {
        const int n = b;
        const float* row = W + (size_t)n * K_DIM;
        float4 v[4];
#pragma unroll
        for (int i = 0; i < 4; i++) v[i] = *(const float4*)(row + t * 16 + i * 4);

        float amax = 0.f;
#pragma unroll
        for (int i = 0; i < 4; i++)
            amax = fmaxf(amax, fmaxf(fmaxf(fabsf(v[i].x), fabsf(v[i].y)),
                                     fmaxf(fabsf(v[i].z), fabsf(v[i].w))));
#pragma unroll
        for (int o = 16; o > 0; o >>= 1)
            amax = fmaxf(amax, __shfl_xor_sync(0xffffffffu, amax, o));
        if (lid == 0) smx[wid] = amax;
        __syncthreads();
        float gmax = smx[0];
#pragma unroll
        for (int i = 1; i < 8; i++) gmax = fmaxf(gmax, smx[i]);
        const float scale = (gmax > 0.f) ? gmax / 127.0f : 1.0f;
        if (t == 0) g_wscale[n] = scale;

        __half2 h[8];
#pragma unroll
        for (int i = 0; i < 4; i++) {
            float q0 = fminf(fmaxf(rintf(v[i].x / scale), -127.f), 127.f);
            float q1 = fminf(fmaxf(rintf(v[i].y / scale), -127.f), 127.f);
            float q2 = fminf(fmaxf(rintf(v[i].z / scale), -127.f), 127.f);
            float q3 = fminf(fmaxf(rintf(v[i].w / scale), -127.f), 127.f);
            h[2 * i]     = __floats2half2_rn(q0, q1);
            h[2 * i + 1] = __floats2half2_rn(q2, q3);
        }
        int4* dst = (int4*)(g_Wh + (size_t)n * K_DIM + t * 16);
        dst[0] = *(int4*)&h[0];
        dst[1] = *(int4*)&h[4];
    } else {
        const int m = b - N_DIM;
        const float* row = X + (size_t)m * K_DIM;
        float4 v[4];
#pragma unroll
        for (int i = 0; i < 4; i++) v[i] = *(const float4*)(row + t * 16 + i * 4);

        float lmin = v[0].x, lmax = v[0].x;
#pragma unroll
        for (int i = 0; i < 4; i++) {
            lmin = fminf(lmin, fminf(fminf(v[i].x, v[i].y), fminf(v[i].z, v[i].w)));
            lmax = fmaxf(lmax, fmaxf(fmaxf(v[i].x, v[i].y), fmaxf(v[i].z, v[i].w)));
        }
#pragma unroll
        for (int o = 16; o > 0; o >>= 1) {
            lmin = fminf(lmin, __shfl_xor_sync(0xffffffffu, lmin, o));
            lmax = fmaxf(lmax, __shfl_xor_sync(0xffffffffu, lmax, o));
        }
        if (lid == 0) { smn[wid] = lmin; smx[wid] = lmax; }
        __syncthreads();
        float gmin = smn[0], gmax = smx[0];
#pragma unroll
        for (int i = 1; i < 8; i++) { gmin = fminf(gmin, smn[i]); gmax = fmaxf(gmax, smx[i]); }

        const float rng   = gmax - gmin;
        const float scale = (rng > 0.f) ? rng / 255.0f : 1.0f;
        const float zp    = rintf(-gmin / scale);
        if (t == 0) g_ascale[m] = scale;

        __half2 h[8];
#pragma unroll
        for (int i = 0; i < 4; i++) {
            float q0 = fminf(fmaxf(rintf(v[i].x / scale) + zp, 0.f), 255.f) - zp;
            float q1 = fminf(fmaxf(rintf(v[i].y / scale) + zp, 0.f), 255.f) - zp;
            float q2 = fminf(fmaxf(rintf(v[i].z / scale) + zp, 0.f), 255.f) - zp;
            float q3 = fminf(fmaxf(rintf(v[i].w / scale) + zp, 0.f), 255.f) - zp;
            h[2 * i]     = __floats2half2_rn(q0, q1);
            h[2 * i + 1] = __floats2half2_rn(q2, q3);
        }
        int4* dst = (int4*)(g_Xh + (size_t)m * K_DIM + t * 16);
        dst[0] = *(int4*)&h[0];
        dst[1] = *(int4*)&h[4];
    }
}

// ---------------- fp16 tensor-core GEMM ----------------
// 128x256 tile, BK=64 halfs (128B), 4-stage cp.async, 16 warps (4m x 4n), warp tile 32x64.
// SMEM rows 128B with XOR-8 chunk swizzle: phys_chunk = chunk ^ (row & 7).
// Inner loop interleaves each B ldmatrix with its 4 dependent MMAs (latency overlap).
__global__ __launch_bounds__(512, 1) void gemm_kernel(const float* __restrict__ bias,
                                                      float* __restrict__ out) {
    extern __shared__ __align__(16) char smem[];
    const uint32_t sb = smem_u32(smem);
    const int tid  = threadIdx.x;
    const int warp = tid >> 5, lane = tid & 31;
    const int wm = warp >> 2, wn = warp & 3;
    const int m0 = blockIdx.y * BM, n0 = blockIdx.x * BN;

    float* s_sw = (float*)(smem + OFF_TAB);
    float* s_bi = (float*)(smem + OFF_TAB + 1024);
    if (tid < 256) {
        s_sw[tid] = g_wscale[n0 + tid];
        s_bi[tid] = bias[n0 + tid];
    }

    const char* Ag = (const char*)g_Xh + (size_t)m0 * K_DIM * 2;
    const char* Bg = (const char*)g_Wh + (size_t)n0 * K_DIM * 2;

#define LOAD_STAGE(s, k) do {                                                      \
        uint32_t ab = sb + (s) * STAGE_BYTES;                                      \
        uint32_t bb = ab + A_TILE;                                                 \
        const char* ag = Ag + (size_t)(k) * 128;                                   \
        const char* bg = Bg + (size_t)(k) * 128;                                   \
        _Pragma("unroll")                                                          \
        for (int it = 0; it < 2; it++) {                                           \
            int idx = tid + it * 512, row = idx >> 3, ch = idx & 7;                \
            cp_async16(ab + row * 128 + ((ch ^ (row & 7)) * 16),                   \
                       ag + (size_t)row * (K_DIM * 2) + ch * 16);                  \
        }                                                                          \
        _Pragma("unroll")                                                          \
        for (int it = 0; it < 4; it++) {                                           \
            int idx = tid + it * 512, row = idx >> 3, ch = idx & 7;                \
            cp_async16(bb + row * 128 + ((ch ^ (row & 7)) * 16),                   \
                       bg + (size_t)row * (K_DIM * 2) + ch * 16);                  \
        }                                                                          \
    } while (0)

    LOAD_STAGE(0, 0); CP_COMMIT();
    LOAD_STAGE(1, 1); CP_COMMIT();
    LOAD_STAGE(2, 2); CP_COMMIT();

    float acc[2][8][4];
#pragma unroll
    for (int i = 0; i < 2; i++)
#pragma unroll
        for (int j = 0; j < 8; j++)
#pragma unroll
            for (int c = 0; c < 4; c++) acc[i][j][c] = 0.f;

    const int lrow = lane & 15;          // row-in-16 for ldmatrix
    const int lhi  = lane >> 4;          // chunk selector (0/1)

    for (int k = 0; k < KIT; k++) {
        const int s = k % NSTG;
        CP_WAIT2();
        __syncthreads();
        if (k + 3 < KIT) LOAD_STAGE((k + 3) % NSTG, k + 3);
        CP_COMMIT();

        const uint32_t abase = sb + s * STAGE_BYTES;
        const uint32_t bbase = abase + A_TILE;

#pragma unroll
        for (int ks = 0; ks < 4; ks++) {
            const int cbase = 2 * ks + lhi;
            uint32_t a[2][4];
#pragma unroll
            for (int i = 0; i < 2; i++) {
                int row = wm * 32 + i * 16 + lrow;
                ldsm_x4(abase + row * 128 + ((cbase ^ (row & 7)) * 16),
                        a[i][0], a[i][1], a[i][2], a[i][3]);
            }
            // interleave: each B ldmatrix immediately feeds its 4 MMAs,
            // letting the next ldmatrix overlap tensor-pipe execution
#pragma unroll
            for (int jp = 0; jp < 4; jp++) {
                int row = wn * 64 + jp * 16 + lrow;
                uint32_t r0, r1, r2, r3;
                ldsm_x4(bbase + row * 128 + ((cbase ^ (row & 7)) * 16), r0, r1, r2, r3);
                mma_f16(acc[0][2 * jp],     a[0], r0, r2);
                mma_f16(acc[1][2 * jp],     a[1], r0, r2);
                mma_f16(acc[0][2 * jp + 1], a[0], r1, r3);
                mma_f16(acc[1][2 * jp + 1], a[1], r1, r3);
            }
        }
    }
    __syncthreads();

    // ---------------- epilogue: Y = acc * (sa*sw) + bias ----------------
    const int g  = lane >> 2;
    const int cl = (lane & 3) * 2;
    float sa[2][2]; int grow[2][2];
#pragma unroll
    for (int i = 0; i < 2; i++)
#pragma unroll
        for (int h = 0; h < 2; h++) {
            int r = m0 + wm * 32 + i * 16 + h * 8 + g;
            grow[i][h] = r;
            sa[i][h] = g_ascale[r];
        }

#pragma unroll
    for (int i = 0; i < 2; i++)
#pragma unroll
        for (int j = 0; j < 8; j++) {
            const int lc = wn * 64 + j * 8 + cl;
            const float sw0 = s_sw[lc], sw1 = s_sw[lc + 1];
            const float bi0 = s_bi[lc], bi1 = s_bi[lc + 1];
#pragma unroll
            for (int h = 0; h < 2; h++) {
                const float s0 = sa[i][h];
                float2 v;
                v.x = acc[i][j][h * 2 + 0] * (s0 * sw0) + bi0;
                v.y = acc[i][j][h * 2 + 1] * (s0 * sw1) + bi1;
                *(float2*)(out + (size_t)grow[i][h] * N_DIM + n0 + lc) = v;
            }
        }
#undef LOAD_STAGE
}

// ---------------- launch ----------------
extern "C" void kernel_launch(void* const* d_in, const int* in_sizes, int n_in,
                              void* d_out, int out_size) {
    const float* x    = (const float*)d_in[0];
    const float* w    = (const float*)d_in[1];
    const float* bias = (const float*)d_in[2];
    float* out = (float*)d_out;

    cudaFuncSetAttribute(gemm_kernel, cudaFuncAttributeMaxDynamicSharedMemorySize, SMEM_TOTAL);

    quant_kernel<<<N_DIM + M_DIM, 256>>>(w, x);
    gemm_kernel<<<dim3(N_DIM / BN, M_DIM / BM), 512, SMEM_TOTAL>>>(bias, out);
}

// round 12
// speedup vs baseline: 1.0709x; 1.0709x over previous
#include <cuda_runtime.h>
#include <cuda_fp16.h>
#include <cstdint>

#define K_DIM 4096
#define M_DIM 8192
#define N_DIM 4096

// GEMM tiling: BM=128, BN=128, BK=64 halfs (128B rows), 256 threads (4x2 warps),
// 2 CTAs per SM for barrier decoupling.
#define BM 128
#define BN 128
#define KIT 64                     // K / 64
#define A_TILE 16384               // 128 rows x 128B
#define B_TILE 16384               // 128 rows x 128B
#define STAGE_BYTES (A_TILE + B_TILE)
#define NSTG 3
#define OFF_TAB (NSTG * STAGE_BYTES)
#define SMEM_TOTAL (OFF_TAB + 128 * 8)

// ---------------- scratch (allocation-free) ----------------
__device__ __align__(16) __half g_Wh[(size_t)N_DIM * K_DIM];  // 32MB [N][K]
__device__ __align__(16) __half g_Xh[(size_t)M_DIM * K_DIM];  // 64MB [M][K], holds (Xq - zp)
__device__ float g_wscale[N_DIM];
__device__ float g_ascale[M_DIM];

// ---------------- PTX helpers (base-target safe) ----------------
__device__ __forceinline__ uint32_t smem_u32(const void* p) {
    uint32_t a;
    asm("{ .reg .u64 t; cvta.to.shared.u64 t, %1; cvt.u32.u64 %0, t; }" : "=r"(a) : "l"(p));
    return a;
}
__device__ __forceinline__ void cp_async16(uint32_t dst, const void* src) {
    asm volatile("cp.async.cg.shared.global [%0], [%1], 16;" :: "r"(dst), "l"(src));
}
#define CP_COMMIT() asm volatile("cp.async.commit_group;" ::: "memory")
#define CP_WAIT1()  asm volatile("cp.async.wait_group 1;" ::: "memory")

__device__ __forceinline__ void ldsm_x4(uint32_t addr, uint32_t& r0, uint32_t& r1,
                                        uint32_t& r2, uint32_t& r3) {
    asm volatile("ldmatrix.sync.aligned.m8n8.x4.shared.b16 {%0,%1,%2,%3}, [%4];"
                 : "=r"(r0), "=r"(r1), "=r"(r2), "=r"(r3) : "r"(addr));
}
__device__ __forceinline__ void mma_f16(float* c, const uint32_t* a, uint32_t b0, uint32_t b1) {
    asm volatile("mma.sync.aligned.m16n8k16.row.col.f32.f16.f16.f32 "
                 "{%0,%1,%2,%3}, {%4,%5,%6,%7}, {%8,%9}, {%0,%1,%2,%3};"
                 : "+f"(c[0]), "+f"(c[1]), "+f"(c[2]), "+f"(c[3])
                 : "r"(a[0]), "r"(a[1]), "r"(a[2]), "r"(a[3]), "r"(b0), "r"(b1));
}

// ---------------- fused quantization ----------------
// blocks [0, N) -> weight rows; blocks [N, N+M) -> activation tokens.
__global__ __launch_bounds__(256) void quant_kernel(const float* __restrict__ W,
                                                    const float* __restrict__ X) {
    const int b = blockIdx.x;
    const int t = threadIdx.x, wid = t >> 5, lid = t & 31;
    __shared__ float smn[8], smx[8];

    if (b < N_DIM) {
        const int n = b;
        const float* row = W + (size_t)n * K_DIM;
        float4 v[4];
#pragma unroll
        for (int i = 0; i < 4; i++) v[i] = *(const float4*)(row + t * 16 + i * 4);

        float amax = 0.f;
#pragma unroll
        for (int i = 0; i < 4; i++)
            amax = fmaxf(amax, fmaxf(fmaxf(fabsf(v[i].x), fabsf(v[i].y)),
                                     fmaxf(fabsf(v[i].z), fabsf(v[i].w))));
#pragma unroll
        for (int o = 16; o > 0; o >>= 1)
            amax = fmaxf(amax, __shfl_xor_sync(0xffffffffu, amax, o));
        if (lid == 0) smx[wid] = amax;
        __syncthreads();
        float gmax = smx[0];
#pragma unroll
        for (int i = 1; i < 8; i++) gmax = fmaxf(gmax, smx[i]);
        const float scale = (gmax > 0.f) ? gmax / 127.0f : 1.0f;
        if (t == 0) g_wscale[n] = scale;

        __half2 h[8];
#pragma unroll
        for (int i = 0; i < 4; i++) {
            float q0 = fminf(fmaxf(rintf(v[i].x / scale), -127.f), 127.f);
            float q1 = fminf(fmaxf(rintf(v[i].y / scale), -127.f), 127.f);
            float q2 = fminf(fmaxf(rintf(v[i].z / scale), -127.f), 127.f);
            float q3 = fminf(fmaxf(rintf(v[i].w / scale), -127.f), 127.f);
            h[2 * i]     = __floats2half2_rn(q0, q1);
            h[2 * i + 1] = __floats2half2_rn(q2, q3);
        }
        int4* dst = (int4*)(g_Wh + (size_t)n * K_DIM + t * 16);
        dst[0] = *(int4*)&h[0];
        dst[1] = *(int4*)&h[4];
    } else {
        const int m = b - N_DIM;
        const float* row = X + (size_t)m * K_DIM;
        float4 v[4];
#pragma unroll
        for (int i = 0; i < 4; i++) v[i] = *(const float4*)(row + t * 16 + i * 4);

        float lmin = v[0].x, lmax = v[0].x;
#pragma unroll
        for (int i = 0; i < 4; i++) {
            lmin = fminf(lmin, fminf(fminf(v[i].x, v[i].y), fminf(v[i].z, v[i].w)));
            lmax = fmaxf(lmax, fmaxf(fmaxf(v[i].x, v[i].y), fmaxf(v[i].z, v[i].w)));
        }
#pragma unroll
        for (int o = 16; o > 0; o >>= 1) {
            lmin = fminf(lmin, __shfl_xor_sync(0xffffffffu, lmin, o));
            lmax = fmaxf(lmax, __shfl_xor_sync(0xffffffffu, lmax, o));
        }
        if (lid == 0) { smn[wid] = lmin; smx[wid] = lmax; }
        __syncthreads();
        float gmin = smn[0], gmax = smx[0];
#pragma unroll
        for (int i = 1; i < 8; i++) { gmin = fminf(gmin, smn[i]); gmax = fmaxf(gmax, smx[i]); }

        const float rng   = gmax - gmin;
        const float scale = (rng > 0.f) ? rng / 255.0f : 1.0f;
        const float zp    = rintf(-gmin / scale);
        if (t == 0) g_ascale[m] = scale;

        __half2 h[8];
#pragma unroll
        for (int i = 0; i < 4; i++) {
            float q0 = fminf(fmaxf(rintf(v[i].x / scale) + zp, 0.f), 255.f) - zp;
            float q1 = fminf(fmaxf(rintf(v[i].y / scale) + zp, 0.f), 255.f) - zp;
            float q2 = fminf(fmaxf(rintf(v[i].z / scale) + zp, 0.f), 255.f) - zp;
            float q3 = fminf(fmaxf(rintf(v[i].w / scale) + zp, 0.f), 255.f) - zp;
            h[2 * i]     = __floats2half2_rn(q0, q1);
            h[2 * i + 1] = __floats2half2_rn(q2, q3);
        }
        int4* dst = (int4*)(g_Xh + (size_t)m * K_DIM + t * 16);
        dst[0] = *(int4*)&h[0];
        dst[1] = *(int4*)&h[4];
    }
}

// ---------------- fp16 tensor-core GEMM ----------------
// 128x128 tile, BK=64 halfs (128B), 3-stage cp.async, 8 warps (4m x 2n), warp tile 32x64.
// 2 CTAs per SM: while one CTA waits at its stage barrier, the other feeds the tensor pipe.
// SMEM rows 128B with XOR-8 chunk swizzle: phys_chunk = chunk ^ (row & 7).
__global__ __launch_bounds__(256, 2) void gemm_kernel(const float* __restrict__ bias,
                                                      float* __restrict__ out) {
    extern __shared__ __align__(16) char smem[];
    const uint32_t sb = smem_u32(smem);
    const int tid  = threadIdx.x;
    const int warp = tid >> 5, lane = tid & 31;
    const int wm = warp >> 1, wn = warp & 1;
    const int m0 = blockIdx.y * BM, n0 = blockIdx.x * BN;

    float* s_sw = (float*)(smem + OFF_TAB);
    float* s_bi = (float*)(smem + OFF_TAB + 512);
    if (tid < 128) {
        s_sw[tid] = g_wscale[n0 + tid];
        s_bi[tid] = bias[n0 + tid];
    }

    const char* Ag = (const char*)g_Xh + (size_t)m0 * K_DIM * 2;
    const char* Bg = (const char*)g_Wh + (size_t)n0 * K_DIM * 2;

#define LOAD_STAGE(s, k) do {                                                      \
        uint32_t ab = sb + (s) * STAGE_BYTES;                                      \
        uint32_t bb = ab + A_TILE;                                                 \
        const char* ag = Ag + (size_t)(k) * 128;                                   \
        const char* bg = Bg + (size_t)(k) * 128;                                   \
        _Pragma("unroll")                                                          \
        for (int it = 0; it < 4; it++) {                                           \
            int idx = tid + it * 256, row = idx >> 3, ch = idx & 7;                \
            cp_async16(ab + row * 128 + ((ch ^ (row & 7)) * 16),                   \
                       ag + (size_t)row * (K_DIM * 2) + ch * 16);                  \
        }                                                                          \
        _Pragma("unroll")                                                          \
        for (int it = 0; it < 4; it++) {                                           \
            int idx = tid + it * 256, row = idx >> 3, ch = idx & 7;                \
            cp_async16(bb + row * 128 + ((ch ^ (row & 7)) * 16),                   \
                       bg + (size_t)row * (K_DIM * 2) + ch * 16);                  \
        }                                                                          \
    } while (0)

    LOAD_STAGE(0, 0); CP_COMMIT();
    LOAD_STAGE(1, 1); CP_COMMIT();

    float acc[2][8][4];
#pragma unroll
    for (int i = 0; i < 2; i++)
#pragma unroll
        for (int j = 0; j < 8; j++)
#pragma unroll
            for (int c = 0; c < 4; c++) acc[i][j][c] = 0.f;

    const int lrow = lane & 15;          // row-in-16 for ldmatrix
    const int lhi  = lane >> 4;          // chunk selector (0/1)

    for (int k = 0; k < KIT; k++) {
        const int s = k % NSTG;
        CP_WAIT1();
        __syncthreads();
        if (k + 2 < KIT) LOAD_STAGE((k + 2) % NSTG, k + 2);
        CP_COMMIT();

        const uint32_t abase = sb + s * STAGE_BYTES;
        const uint32_t bbase = abase + A_TILE;

#pragma unroll
        for (int ks = 0; ks < 4; ks++) {
            const int cbase = 2 * ks + lhi;
            uint32_t a[2][4];
#pragma unroll
            for (int i = 0; i < 2; i++) {
                int row = wm * 32 + i * 16 + lrow;
                ldsm_x4(abase + row * 128 + ((cbase ^ (row & 7)) * 16),
                        a[i][0], a[i][1], a[i][2], a[i][3]);
            }
            // interleave: each B ldmatrix immediately feeds its 4 MMAs
#pragma unroll
            for (int jp = 0; jp < 4; jp++) {
                int row = wn * 64 + jp * 16 + lrow;
                uint32_t r0, r1, r2, r3;
                ldsm_x4(bbase + row * 128 + ((cbase ^ (row & 7)) * 16), r0, r1, r2, r3);
                mma_f16(acc[0][2 * jp],     a[0], r0, r2);
                mma_f16(acc[1][2 * jp],     a[1], r0, r2);
                mma_f16(acc[0][2 * jp + 1], a[0], r1, r3);
                mma_f16(acc[1][2 * jp + 1], a[1], r1, r3);
            }
        }
    }
    __syncthreads();

    // ---------------- epilogue: Y = acc * (sa*sw) + bias ----------------
    const int g  = lane >> 2;
    const int cl = (lane & 3) * 2;
    float sa[2][2]; int grow[2][2];
#pragma unroll
    for (int i = 0; i < 2; i++)
#pragma unroll
        for (int h = 0; h < 2; h++) {
            int r = m0 + wm * 32 + i * 16 + h * 8 + g;
            grow[i][h] = r;
            sa[i][h] = g_ascale[r];
        }

#pragma unroll
    for (int i = 0; i < 2; i++)
#pragma unroll
        for (int j = 0; j < 8; j++) {
            const int lc = wn * 64 + j * 8 + cl;
            const float sw0 = s_sw[lc], sw1 = s_sw[lc + 1];
            const float bi0 = s_bi[lc], bi1 = s_bi[lc + 1];
#pragma unroll
            for (int h = 0; h < 2; h++) {
                const float s0 = sa[i][h];
                float2 v;
                v.x = acc[i][j][h * 2 + 0] * (s0 * sw0) + bi0;
                v.y = acc[i][j][h * 2 + 1] * (s0 * sw1) + bi1;
                *(float2*)(out + (size_t)grow[i][h] * N_DIM + n0 + lc) = v;
            }
        }
#undef LOAD_STAGE
}

// ---------------- launch ----------------
extern "C" void kernel_launch(void* const* d_in, const int* in_sizes, int n_in,
                              void* d_out, int out_size) {
    const float* x    = (const float*)d_in[0];
    const float* w    = (const float*)d_in[1];
    const float* bias = (const float*)d_in[2];
    float* out = (float*)d_out;

    cudaFuncSetAttribute(gemm_kernel, cudaFuncAttributeMaxDynamicSharedMemorySize, SMEM_TOTAL);

    quant_kernel<<<N_DIM + M_DIM, 256>>>(w, x);
    gemm_kernel<<<dim3(N_DIM / BN, M_DIM / BM), 256, SMEM_TOTAL>>>(bias, out);
}

// round 13
// speedup vs baseline: 1.1127x; 1.0391x over previous
#include <cuda_runtime.h>
#include <cuda_fp16.h>
#include <cstdint>

#define K_DIM 4096
#define M_DIM 8192
#define N_DIM 4096

// GEMM tiling: BM=128, BN=128, BK=64 halfs (128B rows), 256 threads (4x2 warps),
// 2 CTAs per SM for barrier decoupling.
#define BM 128
#define BN 128
#define KIT 64                     // K / 64
#define A_TILE 16384               // 128 rows x 128B
#define B_TILE 16384               // 128 rows x 128B
#define STAGE_BYTES (A_TILE + B_TILE)
#define NSTG 3
#define OFF_TAB (NSTG * STAGE_BYTES)
#define SMEM_TOTAL (OFF_TAB + 128 * 8)

// ---------------- scratch (allocation-free) ----------------
__device__ __align__(16) __half g_Wh[(size_t)N_DIM * K_DIM];  // 32MB [N][K]
__device__ __align__(16) __half g_Xh[(size_t)M_DIM * K_DIM];  // 64MB [M][K], holds (Xq - zp)
__device__ float g_wscale[N_DIM];
__device__ float g_ascale[M_DIM];

// ---------------- PTX helpers (base-target safe) ----------------
__device__ __forceinline__ uint32_t smem_u32(const void* p) {
    uint32_t a;
    asm("{ .reg .u64 t; cvta.to.shared.u64 t, %1; cvt.u32.u64 %0, t; }" : "=r"(a) : "l"(p));
    return a;
}
__device__ __forceinline__ void cp_async16(uint32_t dst, const void* src) {
    asm volatile("cp.async.cg.shared.global [%0], [%1], 16;" :: "r"(dst), "l"(src));
}
#define CP_COMMIT() asm volatile("cp.async.commit_group;" ::: "memory")
#define CP_WAIT1()  asm volatile("cp.async.wait_group 1;" ::: "memory")

__device__ __forceinline__ void ldsm_x4(uint32_t addr, uint32_t& r0, uint32_t& r1,
                                        uint32_t& r2, uint32_t& r3) {
    asm volatile("ldmatrix.sync.aligned.m8n8.x4.shared.b16 {%0,%1,%2,%3}, [%4];"
                 : "=r"(r0), "=r"(r1), "=r"(r2), "=r"(r3) : "r"(addr));
}
__device__ __forceinline__ void mma_f16(float* c, const uint32_t* a, uint32_t b0, uint32_t b1) {
    asm volatile("mma.sync.aligned.m16n8k16.row.col.f32.f16.f16.f32 "
                 "{%0,%1,%2,%3}, {%4,%5,%6,%7}, {%8,%9}, {%0,%1,%2,%3};"
                 : "+f"(c[0]), "+f"(c[1]), "+f"(c[2]), "+f"(c[3])
                 : "r"(a[0]), "r"(a[1]), "r"(a[2]), "r"(a[3]), "r"(b0), "r"(b1));
}

// ---------------- fused quantization ----------------
// blocks [0, N) -> weight rows; blocks [N, N+M) -> activation tokens.
__global__ __launch_bounds__(256) void quant_kernel(const float* __restrict__ W,
                                                    const float* __restrict__ X) {
    const int b = blockIdx.x;
    const int t = threadIdx.x, wid = t >> 5, lid = t & 31;
    __shared__ float smn[8], smx[8];

    if (b < N_DIM) {
        const int n = b;
        const float* row = W + (size_t)n * K_DIM;
        float4 v[4];
#pragma unroll
        for (int i = 0; i < 4; i++) v[i] = *(const float4*)(row + t * 16 + i * 4);

        float amax = 0.f;
#pragma unroll
        for (int i = 0; i < 4; i++)
            amax = fmaxf(amax, fmaxf(fmaxf(fabsf(v[i].x), fabsf(v[i].y)),
                                     fmaxf(fabsf(v[i].z), fabsf(v[i].w))));
#pragma unroll
        for (int o = 16; o > 0; o >>= 1)
            amax = fmaxf(amax, __shfl_xor_sync(0xffffffffu, amax, o));
        if (lid == 0) smx[wid] = amax;
        __syncthreads();
        float gmax = smx[0];
#pragma unroll
        for (int i = 1; i < 8; i++) gmax = fmaxf(gmax, smx[i]);
        const float scale = (gmax > 0.f) ? gmax / 127.0f : 1.0f;
        if (t == 0) g_wscale[n] = scale;

        __half2 h[8];
#pragma unroll
        for (int i = 0; i < 4; i++) {
            float q0 = fminf(fmaxf(rintf(v[i].x / scale), -127.f), 127.f);
            float q1 = fminf(fmaxf(rintf(v[i].y / scale), -127.f), 127.f);
            float q2 = fminf(fmaxf(rintf(v[i].z / scale), -127.f), 127.f);
            float q3 = fminf(fmaxf(rintf(v[i].w / scale), -127.f), 127.f);
            h[2 * i]     = __floats2half2_rn(q0, q1);
            h[2 * i + 1] = __floats2half2_rn(q2, q3);
        }
        int4* dst = (int4*)(g_Wh + (size_t)n * K_DIM + t * 16);
        dst[0] = *(int4*)&h[0];
        dst[1] = *(int4*)&h[4];
    } else {
        const int m = b - N_DIM;
        const float* row = X + (size_t)m * K_DIM;
        float4 v[4];
#pragma unroll
        for (int i = 0; i < 4; i++) v[i] = *(const float4*)(row + t * 16 + i * 4);

        float lmin = v[0].x, lmax = v[0].x;
#pragma unroll
        for (int i = 0; i < 4; i++) {
            lmin = fminf(lmin, fminf(fminf(v[i].x, v[i].y), fminf(v[i].z, v[i].w)));
            lmax = fmaxf(lmax, fmaxf(fmaxf(v[i].x, v[i].y), fmaxf(v[i].z, v[i].w)));
        }
#pragma unroll
        for (int o = 16; o > 0; o >>= 1) {
            lmin = fminf(lmin, __shfl_xor_sync(0xffffffffu, lmin, o));
            lmax = fmaxf(lmax, __shfl_xor_sync(0xffffffffu, lmax, o));
        }
        if (lid == 0) { smn[wid] = lmin; smx[wid] = lmax; }
        __syncthreads();
        float gmin = smn[0], gmax = smx[0];
#pragma unroll
        for (int i = 1; i < 8; i++) { gmin = fminf(gmin, smn[i]); gmax = fmaxf(gmax, smx[i]); }

        const float rng   = gmax - gmin;
        const float scale = (rng > 0.f) ? rng / 255.0f : 1.0f;
        const float zp    = rintf(-gmin / scale);
        if (t == 0) g_ascale[m] = scale;

        __half2 h[8];
#pragma unroll
        for (int i = 0; i < 4; i++) {
            float q0 = fminf(fmaxf(rintf(v[i].x / scale) + zp, 0.f), 255.f) - zp;
            float q1 = fminf(fmaxf(rintf(v[i].y / scale) + zp, 0.f), 255.f) - zp;
            float q2 = fminf(fmaxf(rintf(v[i].z / scale) + zp, 0.f), 255.f) - zp;
            float q3 = fminf(fmaxf(rintf(v[i].w / scale) + zp, 0.f), 255.f) - zp;
            h[2 * i]     = __floats2half2_rn(q0, q1);
            h[2 * i + 1] = __floats2half2_rn(q2, q3);
        }
        int4* dst = (int4*)(g_Xh + (size_t)m * K_DIM + t * 16);
        dst[0] = *(int4*)&h[0];
        dst[1] = *(int4*)&h[4];
    }
}

// ---------------- fp16 tensor-core GEMM ----------------
// 128x128 tile, BK=64 halfs (128B), 3-stage cp.async, 8 warps (4m x 2n), warp tile 32x64.
// 2 CTAs per SM. Post-barrier critical path: ks=0 fragments+MMAs issue FIRST, then
// the next stage's cp.async block (LDGSTS issue cost overlaps tensor execution).
// Stage offsets advance incrementally (no modulo in the hot loop).
__global__ __launch_bounds__(256, 2) void gemm_kernel(const float* __restrict__ bias,
                                                      float* __restrict__ out) {
    extern __shared__ __align__(16) char smem[];
    const uint32_t sb = smem_u32(smem);
    const int tid  = threadIdx.x;
    const int warp = tid >> 5, lane = tid & 31;
    const int wm = warp >> 1, wn = warp & 1;
    const int m0 = blockIdx.y * BM, n0 = blockIdx.x * BN;

    float* s_sw = (float*)(smem + OFF_TAB);
    float* s_bi = (float*)(smem + OFF_TAB + 512);
    if (tid < 128) {
        s_sw[tid] = g_wscale[n0 + tid];
        s_bi[tid] = bias[n0 + tid];
    }

    const char* Ag = (const char*)g_Xh + (size_t)m0 * K_DIM * 2;
    const char* Bg = (const char*)g_Wh + (size_t)n0 * K_DIM * 2;

#define LOAD_STAGE_OFF(soff, k) do {                                               \
        uint32_t ab = sb + (soff);                                                 \
        uint32_t bb = ab + A_TILE;                                                 \
        const char* ag = Ag + (size_t)(k) * 128;                                   \
        const char* bg = Bg + (size_t)(k) * 128;                                   \
        _Pragma("unroll")                                                          \
        for (int it = 0; it < 4; it++) {                                           \
            int idx = tid + it * 256, row = idx >> 3, ch = idx & 7;                \
            cp_async16(ab + row * 128 + ((ch ^ (row & 7)) * 16),                   \
                       ag + (size_t)row * (K_DIM * 2) + ch * 16);                  \
        }                                                                          \
        _Pragma("unroll")                                                          \
        for (int it = 0; it < 4; it++) {                                           \
            int idx = tid + it * 256, row = idx >> 3, ch = idx & 7;                \
            cp_async16(bb + row * 128 + ((ch ^ (row & 7)) * 16),                   \
                       bg + (size_t)row * (K_DIM * 2) + ch * 16);                  \
        }                                                                          \
    } while (0)

// one k16 slice: A fragments + interleaved B ldsm / MMA
#define DO_KS(ks) do {                                                             \
        const int cbase = 2 * (ks) + lhi;                                          \
        uint32_t a[2][4];                                                          \
        _Pragma("unroll")                                                          \
        for (int i = 0; i < 2; i++) {                                              \
            int row = wm * 32 + i * 16 + lrow;                                     \
            ldsm_x4(abase + row * 128 + ((cbase ^ (row & 7)) * 16),                \
                    a[i][0], a[i][1], a[i][2], a[i][3]);                           \
        }                                                                          \
        _Pragma("unroll")                                                          \
        for (int jp = 0; jp < 4; jp++) {                                           \
            int row = wn * 64 + jp * 16 + lrow;                                    \
            uint32_t r0, r1, r2, r3;                                               \
            ldsm_x4(bbase + row * 128 + ((cbase ^ (row & 7)) * 16), r0, r1, r2, r3);\
            mma_f16(acc[0][2 * jp],     a[0], r0, r2);                             \
            mma_f16(acc[1][2 * jp],     a[1], r0, r2);                             \
            mma_f16(acc[0][2 * jp + 1], a[0], r1, r3);                             \
            mma_f16(acc[1][2 * jp + 1], a[1], r1, r3);                             \
        }                                                                          \
    } while (0)

    LOAD_STAGE_OFF(0, 0); CP_COMMIT();
    LOAD_STAGE_OFF(STAGE_BYTES, 1); CP_COMMIT();

    float acc[2][8][4];
#pragma unroll
    for (int i = 0; i < 2; i++)
#pragma unroll
        for (int j = 0; j < 8; j++)
#pragma unroll
            for (int c = 0; c < 4; c++) acc[i][j][c] = 0.f;

    const int lrow = lane & 15;          // row-in-16 for ldmatrix
    const int lhi  = lane >> 4;          // chunk selector (0/1)

    uint32_t soff = 0;                        // compute-stage byte offset
    uint32_t loff = 2 * STAGE_BYTES;          // load-stage byte offset (k+2)

    for (int k = 0; k < KIT; k++) {
        CP_WAIT1();
        __syncthreads();
        const uint32_t abase = sb + soff;
        const uint32_t bbase = abase + A_TILE;

        // start tensor pipe immediately after the barrier
        DO_KS(0);
        // overlap next-stage cp.async issue with tensor execution
        if (k + 2 < KIT) LOAD_STAGE_OFF(loff, k + 2);
        CP_COMMIT();
        DO_KS(1);
        DO_KS(2);
        DO_KS(3);

        soff += STAGE_BYTES; if (soff == NSTG * STAGE_BYTES) soff = 0;
        loff += STAGE_BYTES; if (loff == NSTG * STAGE_BYTES) loff = 0;
    }
    __syncthreads();

    // ---------------- epilogue: Y = acc * (sa*sw) + bias ----------------
    const int g  = lane >> 2;
    const int cl = (lane & 3) * 2;
    float sa[2][2]; int grow[2][2];
#pragma unroll
    for (int i = 0; i < 2; i++)
#pragma unroll
        for (int h = 0; h < 2; h++) {
            int r = m0 + wm * 32 + i * 16 + h * 8 + g;
            grow[i][h] = r;
            sa[i][h] = g_ascale[r];
        }

#pragma unroll
    for (int i = 0; i < 2; i++)
#pragma unroll
        for (int j = 0; j < 8; j++) {
            const int lc = wn * 64 + j * 8 + cl;
            const float sw0 = s_sw[lc], sw1 = s_sw[lc + 1];
            const float bi0 = s_bi[lc], bi1 = s_bi[lc + 1];
#pragma unroll
            for (int h = 0; h < 2; h++) {
                const float s0 = sa[i][h];
                float2 v;
                v.x = acc[i][j][h * 2 + 0] * (s0 * sw0) + bi0;
                v.y = acc[i][j][h * 2 + 1] * (s0 * sw1) + bi1;
                *(float2*)(out + (size_t)grow[i][h] * N_DIM + n0 + lc) = v;
            }
        }
#undef LOAD_STAGE_OFF
#undef DO_KS
}

// ---------------- launch ----------------
extern "C" void kernel_launch(void* const* d_in, const int* in_sizes, int n_in,
                              void* d_out, int out_size) {
    const float* x    = (const float*)d_in[0];
    const float* w    = (const float*)d_in[1];
    const float* bias = (const float*)d_in[2];
    float* out = (float*)d_out;

    cudaFuncSetAttribute(gemm_kernel, cudaFuncAttributeMaxDynamicSharedMemorySize, SMEM_TOTAL);

    quant_kernel<<<N_DIM + M_DIM, 256>>>(w, x);
    gemm_kernel<<<dim3(N_DIM / BN, M_DIM / BM), 256, SMEM_TOTAL>>>(bias, out);
}

// round 15
// speedup vs baseline: 1.1358x; 1.0208x over previous
#include <cuda_runtime.h>
#include <cuda_fp16.h>
#include <cstdint>

#define K_DIM 4096
#define M_DIM 8192
#define N_DIM 4096

// GEMM tiling: BM=128, BN=128, BK=64 halfs (128B rows), 256 threads (4x2 warps),
// 2 CTAs per SM for barrier decoupling.
#define BM 128
#define BN 128
#define KIT 64                     // K / 64
#define A_TILE 16384               // 128 rows x 128B
#define B_TILE 16384               // 128 rows x 128B
#define STAGE_BYTES (A_TILE + B_TILE)
#define NSTG 3
#define OFF_TAB (NSTG * STAGE_BYTES)
#define SMEM_TOTAL (OFF_TAB + 128 * 8)

// ---------------- scratch (allocation-free) ----------------
__device__ __align__(16) __half g_Wh[(size_t)N_DIM * K_DIM];  // 32MB [N][K]
__device__ __align__(16) __half g_Xh[(size_t)M_DIM * K_DIM];  // 64MB [M][K], holds (Xq - zp)
__device__ float g_wscale[N_DIM];
__device__ float g_ascale[M_DIM];

// ---------------- PTX helpers (base-target safe) ----------------
__device__ __forceinline__ uint32_t smem_u32(const void* p) {
    uint32_t a;
    asm("{ .reg .u64 t; cvta.to.shared.u64 t, %1; cvt.u32.u64 %0, t; }" : "=r"(a) : "l"(p));
    return a;
}
__device__ __forceinline__ void cp_async16(uint32_t dst, const void* src) {
    asm volatile("cp.async.cg.shared.global [%0], [%1], 16;" :: "r"(dst), "l"(src));
}
#define CP_COMMIT() asm volatile("cp.async.commit_group;" ::: "memory")
#define CP_WAIT1()  asm volatile("cp.async.wait_group 1;" ::: "memory")

__device__ __forceinline__ void ldsm_x4(uint32_t addr, uint32_t& r0, uint32_t& r1,
                                        uint32_t& r2, uint32_t& r3) {
    asm volatile("ldmatrix.sync.aligned.m8n8.x4.shared.b16 {%0,%1,%2,%3}, [%4];"
                 : "=r"(r0), "=r"(r1), "=r"(r2), "=r"(r3) : "r"(addr));
}
__device__ __forceinline__ void mma_f16(float* c, const uint32_t* a, uint32_t b0, uint32_t b1) {
    asm volatile("mma.sync.aligned.m16n8k16.row.col.f32.f16.f16.f32 "
                 "{%0,%1,%2,%3}, {%4,%5,%6,%7}, {%8,%9}, {%0,%1,%2,%3};"
                 : "+f"(c[0]), "+f"(c[1]), "+f"(c[2]), "+f"(c[3])
                 : "r"(a[0]), "r"(a[1]), "r"(a[2]), "r"(a[3]), "r"(b0), "r"(b1));
}

// ---------------- fused quantization ----------------
// blocks [0, N) -> weight rows; blocks [N, N+M) -> activation tokens.
__global__ __launch_bounds__(256) void quant_kernel(const float* __restrict__ W,
                                                    const float* __restrict__ X) {
    const int b = blockIdx.x;
    const int t = threadIdx.x, wid = t >> 5, lid = t & 31;
    __shared__ float smn[8], smx[8];

    if (b < N_DIM) {
        const int n = b;
        const float* row = W + (size_t)n * K_DIM;
        float4 v[4];
#pragma unroll
        for (int i = 0; i < 4; i++) v[i] = *(const float4*)(row + t * 16 + i * 4);

        float amax = 0.f;
#pragma unroll
        for (int i = 0; i < 4; i++)
            amax = fmaxf(amax, fmaxf(fmaxf(fabsf(v[i].x), fabsf(v[i].y)),
                                     fmaxf(fabsf(v[i].z), fabsf(v[i].w))));
#pragma unroll
        for (int o = 16; o > 0; o >>= 1)
            amax = fmaxf(amax, __shfl_xor_sync(0xffffffffu, amax, o));
        if (lid == 0) smx[wid] = amax;
        __syncthreads();
        float gmax = smx[0];
#pragma unroll
        for (int i = 1; i < 8; i++) gmax = fmaxf(gmax, smx[i]);
        const float scale = (gmax > 0.f) ? gmax / 127.0f : 1.0f;
        if (t == 0) g_wscale[n] = scale;

        __half2 h[8];
#pragma unroll
        for (int i = 0; i < 4; i++) {
            float q0 = fminf(fmaxf(rintf(v[i].x / scale), -127.f), 127.f);
            float q1 = fminf(fmaxf(rintf(v[i].y / scale), -127.f), 127.f);
            float q2 = fminf(fmaxf(rintf(v[i].z / scale), -127.f), 127.f);
            float q3 = fminf(fmaxf(rintf(v[i].w / scale), -127.f), 127.f);
            h[2 * i]     = __floats2half2_rn(q0, q1);
            h[2 * i + 1] = __floats2half2_rn(q2, q3);
        }
        int4* dst = (int4*)(g_Wh + (size_t)n * K_DIM + t * 16);
        dst[0] = *(int4*)&h[0];
        dst[1] = *(int4*)&h[4];
    } else {
        const int m = b - N_DIM;
        const float* row = X + (size_t)m * K_DIM;
        float4 v[4];
#pragma unroll
        for (int i = 0; i < 4; i++) v[i] = *(const float4*)(row + t * 16 + i * 4);

        float lmin = v[0].x, lmax = v[0].x;
#pragma unroll
        for (int i = 0; i < 4; i++) {
            lmin = fminf(lmin, fminf(fminf(v[i].x, v[i].y), fminf(v[i].z, v[i].w)));
            lmax = fmaxf(lmax, fmaxf(fmaxf(v[i].x, v[i].y), fmaxf(v[i].z, v[i].w)));
        }
#pragma unroll
        for (int o = 16; o > 0; o >>= 1) {
            lmin = fminf(lmin, __shfl_xor_sync(0xffffffffu, lmin, o));
            lmax = fmaxf(lmax, __shfl_xor_sync(0xffffffffu, lmax, o));
        }
        if (lid == 0) { smn[wid] = lmin; smx[wid] = lmax; }
        __syncthreads();
        float gmin = smn[0], gmax = smx[0];
#pragma unroll
        for (int i = 1; i < 8; i++) { gmin = fminf(gmin, smn[i]); gmax = fmaxf(gmax, smx[i]); }

        const float rng   = gmax - gmin;
        const float scale = (rng > 0.f) ? rng / 255.0f : 1.0f;
        const float zp    = rintf(-gmin / scale);
        if (t == 0) g_ascale[m] = scale;

        __half2 h[8];
#pragma unroll
        for (int i = 0; i < 4; i++) {
            float q0 = fminf(fmaxf(rintf(v[i].x / scale) + zp, 0.f), 255.f) - zp;
            float q1 = fminf(fmaxf(rintf(v[i].y / scale) + zp, 0.f), 255.f) - zp;
            float q2 = fminf(fmaxf(rintf(v[i].z / scale) + zp, 0.f), 255.f) - zp;
            float q3 = fminf(fmaxf(rintf(v[i].w / scale) + zp, 0.f), 255.f) - zp;
            h[2 * i]     = __floats2half2_rn(q0, q1);
            h[2 * i + 1] = __floats2half2_rn(q2, q3);
        }
        int4* dst = (int4*)(g_Xh + (size_t)m * K_DIM + t * 16);
        dst[0] = *(int4*)&h[0];
        dst[1] = *(int4*)&h[4];
    }
}

// ---------------- fp16 tensor-core GEMM ----------------
// 128x128 tile, BK=64 halfs (128B), 3-stage cp.async, 8 warps (4m x 2n), warp tile 32x64.
// 2 CTAs per SM. Warp-rotated slice order: warp w processes k16-slices in order
// (w, w+1, w+2, w+3) mod 4 so per-SMSP ldsm bursts and MMA phases interleave
// across warps instead of stalling in lockstep after each barrier.
__global__ __launch_bounds__(256, 2) void gemm_kernel(const float* __restrict__ bias,
                                                      float* __restrict__ out) {
    extern __shared__ __align__(16) char smem[];
    const uint32_t sb = smem_u32(smem);
    const int tid  = threadIdx.x;
    const int warp = tid >> 5, lane = tid & 31;
    const int wm = warp >> 1, wn = warp & 1;
    const int m0 = blockIdx.y * BM, n0 = blockIdx.x * BN;

    float* s_sw = (float*)(smem + OFF_TAB);
    float* s_bi = (float*)(smem + OFF_TAB + 512);
    if (tid < 128) {
        s_sw[tid] = g_wscale[n0 + tid];
        s_bi[tid] = bias[n0 + tid];
    }

    const char* Ag = (const char*)g_Xh + (size_t)m0 * K_DIM * 2;
    const char* Bg = (const char*)g_Wh + (size_t)n0 * K_DIM * 2;

#define LOAD_STAGE_OFF(soff, k) do {                                               \
        uint32_t ab = sb + (soff);                                                 \
        uint32_t bb = ab + A_TILE;                                                 \
        const char* ag = Ag + (size_t)(k) * 128;                                   \
        const char* bg = Bg + (size_t)(k) * 128;                                   \
        _Pragma("unroll")                                                          \
        for (int it = 0; it < 4; it++) {                                           \
            int idx = tid + it * 256, row = idx >> 3, ch = idx & 7;                \
            cp_async16(ab + row * 128 + ((ch ^ (row & 7)) * 16),                   \
                       ag + (size_t)row * (K_DIM * 2) + ch * 16);                  \
        }                                                                          \
        _Pragma("unroll")                                                          \
        for (int it = 0; it < 4; it++) {                                           \
            int idx = tid + it * 256, row = idx >> 3, ch = idx & 7;                \
            cp_async16(bb + row * 128 + ((ch ^ (row & 7)) * 16),                   \
                       bg + (size_t)row * (K_DIM * 2) + ch * 16);                  \
        }                                                                          \
    } while (0)

// one k16 slice (ks may be a runtime value): A fragments + interleaved B ldsm / MMA
#define DO_KS(ks) do {                                                             \
        const int cbase = 2 * (ks) + lhi;                                          \
        uint32_t a[2][4];                                                          \
        _Pragma("unroll")                                                          \
        for (int i = 0; i < 2; i++) {                                              \
            int row = wm * 32 + i * 16 + lrow;                                     \
            ldsm_x4(abase + row * 128 + ((cbase ^ (row & 7)) * 16),                \
                    a[i][0], a[i][1], a[i][2], a[i][3]);                           \
        }                                                                          \
        _Pragma("unroll")                                                          \
        for (int jp = 0; jp < 4; jp++) {                                           \
            int row = wn * 64 + jp * 16 + lrow;                                    \
            uint32_t r0, r1, r2, r3;                                               \
            ldsm_x4(bbase + row * 128 + ((cbase ^ (row & 7)) * 16), r0, r1, r2, r3);\
            mma_f16(acc[0][2 * jp],     a[0], r0, r2);                             \
            mma_f16(acc[1][2 * jp],     a[1], r0, r2);                             \
            mma_f16(acc[0][2 * jp + 1], a[0], r1, r3);                             \
            mma_f16(acc[1][2 * jp + 1], a[1], r1, r3);                             \
        }                                                                          \
    } while (0)

// one full k-iteration body; LOAD is a statement executed after the first slice
#define K_ITER(kload_stmt) do {                                                    \
        CP_WAIT1();                                                                \
        __syncthreads();                                                           \
        const uint32_t abase = sb + soff;                                          \
        const uint32_t bbase = abase + A_TILE;                                     \
        DO_KS(wrot);                                                               \
        kload_stmt;                                                                \
        CP_COMMIT();                                                               \
        DO_KS((wrot + 1) & 3);                                                     \
        DO_KS((wrot + 2) & 3);                                                     \
        DO_KS((wrot + 3) & 3);                                                     \
        soff += STAGE_BYTES; if (soff == NSTG * STAGE_BYTES) soff = 0;             \
        loff += STAGE_BYTES; if (loff == NSTG * STAGE_BYTES) loff = 0;             \
    } while (0)

    LOAD_STAGE_OFF(0, 0); CP_COMMIT();
    LOAD_STAGE_OFF(STAGE_BYTES, 1); CP_COMMIT();

    float acc[2][8][4];
#pragma unroll
    for (int i = 0; i < 2; i++)
#pragma unroll
        for (int j = 0; j < 8; j++)
#pragma unroll
            for (int c = 0; c < 4; c++) acc[i][j][c] = 0.f;

    const int lrow = lane & 15;          // row-in-16 for ldmatrix
    const int lhi  = lane >> 4;          // chunk selector (0/1)
    const int wrot = warp & 3;           // per-warp slice rotation

    uint32_t soff = 0;                        // compute-stage byte offset
    uint32_t loff = 2 * STAGE_BYTES;          // load-stage byte offset (k+2)

    // main loop (prefetch always valid), then 2-iteration tail (no prefetch)
    for (int k = 0; k < KIT - 2; k++) {
        K_ITER(LOAD_STAGE_OFF(loff, k + 2));
    }
    K_ITER((void)0);
    K_ITER((void)0);
    __syncthreads();

    // ---------------- epilogue: Y = acc * (sa*sw) + bias ----------------
    const int g  = lane >> 2;
    const int cl = (lane & 3) * 2;
    float sa[2][2]; int grow[2][2];
#pragma unroll
    for (int i = 0; i < 2; i++)
#pragma unroll
        for (int h = 0; h < 2; h++) {
            int r = m0 + wm * 32 + i * 16 + h * 8 + g;
            grow[i][h] = r;
            sa[i][h] = g_ascale[r];
        }

#pragma unroll
    for (int i = 0; i < 2; i++)
#pragma unroll
        for (int j = 0; j < 8; j++) {
            const int lc = wn * 64 + j * 8 + cl;
            const float sw0 = s_sw[lc], sw1 = s_sw[lc + 1];
            const float bi0 = s_bi[lc], bi1 = s_bi[lc + 1];
#pragma unroll
            for (int h = 0; h < 2; h++) {
                const float s0 = sa[i][h];
                float2 v;
                v.x = acc[i][j][h * 2 + 0] * (s0 * sw0) + bi0;
                v.y = acc[i][j][h * 2 + 1] * (s0 * sw1) + bi1;
                *(float2*)(out + (size_t)grow[i][h] * N_DIM + n0 + lc) = v;
            }
        }
#undef LOAD_STAGE_OFF
#undef DO_KS
#undef K_ITER
}

// ---------------- launch ----------------
extern "C" void kernel_launch(void* const* d_in, const int* in_sizes, int n_in,
                              void* d_out, int out_size) {
    const float* x    = (const float*)d_in[0];
    const float* w    = (const float*)d_in[1];
    const float* bias = (const float*)d_in[2];
    float* out = (float*)d_out;

    cudaFuncSetAttribute(gemm_kernel, cudaFuncAttributeMaxDynamicSharedMemorySize, SMEM_TOTAL);

    quant_kernel<<<N_DIM + M_DIM, 256>>>(w, x);
    gemm_kernel<<<dim3(N_DIM / BN, M_DIM / BM), 256, SMEM_TOTAL>>>(bias, out);
}